// round 15
// baseline (speedup 1.0000x reference)
#include <cuda_runtime.h>
#include <cuda_bf16.h>
#include <math.h>
#include <stdint.h>

#define MAXN   25600
#define D_IN   1068
#define KPADX  1088
#define FDIM   768
#define G4     3072
#define NPE    200
#define MAXDOC 256

typedef unsigned long long ull;

// ---------------- scratch (static device arrays; no allocations) ----------------
__device__ float SC_PE  [NPE * D_IN];
__device__ int   SC_POS [MAXN];
__device__ float SC_WT  [15 * 256 * D_IN];            // taps: 0..2 (k3), 3..7 (k5), 8..14 (k7)
__device__ float SC_FEAT[(size_t)MAXN * FDIM];
__device__ float SC_G   [(size_t)MAXN * G4];
__device__ float SC_CS  [(size_t)MAXN * FDIM];
__device__ unsigned SC_FLAG[128 * 8];                 // padded per-block barrier flags

// bf16 split planes (hi + lo), 16B aligned for cp.async
__device__ __align__(16) __nv_bfloat16 XBh[(size_t)MAXN * KPADX], XBl[(size_t)MAXN * KPADX];
__device__ __align__(16) __nv_bfloat16 WTBh[(size_t)3840 * KPADX], WTBl[(size_t)3840 * KPADX];
__device__ __align__(16) __nv_bfloat16 FBh[(size_t)MAXN * FDIM], FBl[(size_t)MAXN * FDIM];
__device__ __align__(16) __nv_bfloat16 PBh[(size_t)MAXN * FDIM], PBl[(size_t)MAXN * FDIM];
__device__ __align__(16) __nv_bfloat16 HBh[(size_t)MAXN * FDIM], HBl[(size_t)MAXN * FDIM];
__device__ __align__(16) __nv_bfloat16 WGBh[(size_t)4 * G4 * FDIM], WGBl[(size_t)4 * G4 * FDIM];

__device__ __forceinline__ float sigm(float x) { return 1.0f / (1.0f + expf(-x)); }

// ---- mma.sync / ldmatrix / cp.async (base PTX, compute_103-safe) ----
__device__ __forceinline__ uint32_t smem_u32(const void* p) {
    uint32_t a;
    asm("{ .reg .u64 t; cvta.to.shared.u64 t, %1; cvt.u32.u64 %0, t; }" : "=r"(a) : "l"(p));
    return a;
}
__device__ __forceinline__ void ldsm4(uint32_t* r, uint32_t addr) {
    asm volatile("ldmatrix.sync.aligned.m8n8.x4.shared.b16 {%0,%1,%2,%3}, [%4];"
        : "=r"(r[0]), "=r"(r[1]), "=r"(r[2]), "=r"(r[3]) : "r"(addr));
}
__device__ __forceinline__ void mma16816(float* c, const uint32_t* a, uint32_t b0, uint32_t b1) {
    asm volatile("mma.sync.aligned.m16n8k16.row.col.f32.bf16.bf16.f32 "
        "{%0,%1,%2,%3}, {%4,%5,%6,%7}, {%8,%9}, {%0,%1,%2,%3};"
        : "+f"(c[0]), "+f"(c[1]), "+f"(c[2]), "+f"(c[3])
        : "r"(a[0]), "r"(a[1]), "r"(a[2]), "r"(a[3]), "r"(b0), "r"(b1));
}
__device__ __forceinline__ void cpa16(uint32_t dst, const void* src, int valid) {
    asm volatile("cp.async.cg.shared.global [%0], [%1], 16, %2;"
        :: "r"(dst), "l"(src), "r"(valid ? 16 : 0) : "memory");
}
#define CP_COMMIT() asm volatile("cp.async.commit_group;" ::: "memory")
#define CP_WAIT1()  asm volatile("cp.async.wait_group 1;" ::: "memory")
#define CP_WAIT0()  asm volatile("cp.async.wait_group 0;" ::: "memory")

#define RS     80
#define PLANE  10240
#define BUFB   40960
#define SMEM_MMA (2 * BUFB)
// gate M256 tile: A plane 256x32 (20480B), B plane 128x32 (10240B)
#define APL256 20480
#define BUF256 (2 * APL256 + 2 * PLANE)      // 61440
#define SMEM_G256 (2 * BUF256)               // 122880

// load one 128x32 bf16 plane into smem (2 chunks of 16B per thread)
__device__ __forceinline__ void ldp(uint32_t sdst, const __nv_bfloat16* src, int ldk,
                                    int rowBase, int rowLim, int kcol, int tid) {
#pragma unroll
    for (int it = 0; it < 2; ++it) {
        int ch = tid + it * 256;
        int row = ch >> 2, c = ch & 3;
        int r = rowBase + row;
        int v = (r >= 0 && r < rowLim);
        const void* s = src + ((size_t)(v ? r : 0) * ldk + kcol + c * 8);
        cpa16(sdst + row * RS + c * 16, s, v);
    }
}

// load one 256x32 bf16 plane into smem (4 chunks of 16B per thread)
__device__ __forceinline__ void ldp256(uint32_t sdst, const __nv_bfloat16* src, int ldk,
                                       int rowBase, int rowLim, int kcol, int tid) {
#pragma unroll
    for (int it = 0; it < 4; ++it) {
        int ch = tid + it * 256;
        int row = ch >> 2, c = ch & 3;
        int r = rowBase + row;
        int v = (r >= 0 && r < rowLim);
        const void* s = src + ((size_t)(v ? r : 0) * ldk + kcol + c * 8);
        cpa16(sdst + row * RS + c * 16, s, v);
    }
}

// conv per-warp compute on one 32-K block (M128 tile): acc[2][8][4]
__device__ __forceinline__ void wcompute(uint32_t sbuf, int lane, int wm, int wn,
                                         float acc[2][8][4]) {
    int arow = wm * 32 + (lane & 15);
    int brow = wn * 64 + (lane & 7) + ((lane >> 4) << 3);
#pragma unroll
    for (int kh = 0; kh < 2; ++kh) {
        int acol = kh * 16 + ((lane >> 4) << 3);
        int bcol = kh * 16 + (((lane >> 3) & 1) << 3);
        uint32_t ah[2][4], al[2][4];
#pragma unroll
        for (int mt = 0; mt < 2; ++mt) {
            uint32_t ad = sbuf + (arow + mt * 16) * RS + acol * 2;
            ldsm4(ah[mt], ad);
            ldsm4(al[mt], ad + PLANE);
        }
#pragma unroll
        for (int g = 0; g < 4; ++g) {
            uint32_t bh[4], bl[4];
            uint32_t bd = sbuf + 2 * PLANE + (brow + g * 16) * RS + bcol * 2;
            ldsm4(bh, bd);
            ldsm4(bl, bd + PLANE);
#pragma unroll
            for (int mt = 0; mt < 2; ++mt)
#pragma unroll
                for (int sub = 0; sub < 2; ++sub) {
                    int nt = g * 2 + sub;
                    mma16816(acc[mt][nt], ah[mt], bh[sub * 2], bh[sub * 2 + 1]);
                    mma16816(acc[mt][nt], ah[mt], bl[sub * 2], bl[sub * 2 + 1]);
                    mma16816(acc[mt][nt], al[mt], bh[sub * 2], bh[sub * 2 + 1]);
                }
        }
    }
}

// gate per-warp compute on one 32-K block (M256 tile, warp tile 64x64): acc[4][8][4]
__device__ __forceinline__ void wcompute256(uint32_t sbuf, int lane, int wm, int wn,
                                            float acc[4][8][4]) {
    int arow = wm * 64 + (lane & 15);
    int brow = wn * 64 + (lane & 7) + ((lane >> 4) << 3);
#pragma unroll
    for (int kh = 0; kh < 2; ++kh) {
        int acol = kh * 16 + ((lane >> 4) << 3);
        int bcol = kh * 16 + (((lane >> 3) & 1) << 3);
        uint32_t ah[4][4], al[4][4];
#pragma unroll
        for (int mt = 0; mt < 4; ++mt) {
            uint32_t ad = sbuf + (arow + mt * 16) * RS + acol * 2;
            ldsm4(ah[mt], ad);
            ldsm4(al[mt], ad + APL256);
        }
#pragma unroll
        for (int g = 0; g < 4; ++g) {
            uint32_t bh[4], bl[4];
            uint32_t bd = sbuf + 2 * APL256 + (brow + g * 16) * RS + bcol * 2;
            ldsm4(bh, bd);
            ldsm4(bl, bd + PLANE);
#pragma unroll
            for (int mt = 0; mt < 4; ++mt)
#pragma unroll
                for (int sub = 0; sub < 2; ++sub) {
                    int nt = g * 2 + sub;
                    mma16816(acc[mt][nt], ah[mt], bh[sub * 2], bh[sub * 2 + 1]);
                    mma16816(acc[mt][nt], ah[mt], bl[sub * 2], bl[sub * 2 + 1]);
                    mma16816(acc[mt][nt], al[mt], bh[sub * 2], bh[sub * 2 + 1]);
                }
        }
    }
}

// ---------------- fused prep: PE + posidx + conv weight transpose ----------------
__global__ void k_prep(const int* __restrict__ dl, int ndocs, int N,
                       const float* __restrict__ w0, const float* __restrict__ w1,
                       const float* __restrict__ w2) {
    int idx = blockIdx.x * blockDim.x + threadIdx.x;
    if (idx < NPE * D_IN) {
        int pos = idx / D_IN, ch = idx % D_IN;
        int i = ch >> 1;
        float e = (2.0f * (float)i) / (float)D_IN;
        float ang = (float)pos / powf(10000.0f, e);
        SC_PE[idx] = (ch & 1) ? cosf(ang) : sinf(ang);
    }
    const int per = 256 * D_IN;
    if (idx < 15 * per) {
        int t  = idx / per;
        int r  = idx - t * per;
        int oc = r / D_IN;
        int c  = r - oc * D_IN;
        const float* w; int ksz, tl;
        if (t < 3)      { w = w0; ksz = 3; tl = t; }
        else if (t < 8) { w = w1; ksz = 5; tl = t - 3; }
        else            { w = w2; ksz = 7; tl = t - 8; }
        SC_WT[idx] = w[((size_t)oc * D_IN + c) * ksz + tl];
    }
    if (blockIdx.x == 0) {
        __shared__ int off[MAXDOC + 1];
        if (threadIdx.x == 0) {
            int s = 0;
            for (int d = 0; d < ndocs; ++d) { off[d] = s; s += dl[d]; }
            off[ndocs] = s;
        }
        __syncthreads();
        for (int n = threadIdx.x; n < N; n += blockDim.x) {
            int lo = 0, hi = ndocs;
            while (hi - lo > 1) { int mid = (lo + hi) >> 1; if (off[mid] <= n) lo = mid; else hi = mid; }
            SC_POS[n] = n - off[lo];
        }
    }
}

// ---------------- fused: x + PE -> bf16 hi/lo planes ----------------
__global__ void k_addpe_cvt(const float* __restrict__ x, int N) {
    long long idx = (long long)blockIdx.x * blockDim.x + threadIdx.x;
    long long tot = (long long)N * KPADX;
    if (idx >= tot) return;
    int n = (int)(idx / KPADX), k = (int)(idx % KPADX);
    float v = 0.f;
    if (k < D_IN) v = x[(size_t)n * D_IN + k] + SC_PE[SC_POS[n] * D_IN + k];
    __nv_bfloat16 h = __float2bfloat16(v);
    XBh[idx] = h;
    XBl[idx] = __float2bfloat16(v - __bfloat162float(h));
}

// ---------------- fused weight conversions: WT planes + gate weight planes + reset ----------------
__global__ void k_wcvt(const float* __restrict__ s0, const float* __restrict__ s1,
                       const float* __restrict__ s2, const float* __restrict__ s3) {
    long long idx = (long long)blockIdx.x * blockDim.x + threadIdx.x;
    if (idx < (long long)3840 * KPADX) {
        int r = (int)(idx / KPADX), k = (int)(idx % KPADX);
        float v = (k < D_IN) ? SC_WT[(size_t)r * D_IN + k] : 0.f;
        __nv_bfloat16 h = __float2bfloat16(v);
        WTBh[idx] = h;
        WTBl[idx] = __float2bfloat16(v - __bfloat162float(h));
    }
    const long long per = (long long)G4 * FDIM;
    if (idx < 4 * per) {
        int slot = (int)(idx / per);
        long long r = idx - (long long)slot * per;
        const float* s = (slot == 0) ? s0 : (slot == 1) ? s1 : (slot == 2) ? s2 : s3;
        float v = s[r];
        __nv_bfloat16 h = __float2bfloat16(v);
        WGBh[idx] = h;
        WGBl[idx] = __float2bfloat16(v - __bfloat162float(h));
    }
    if (idx < 128 * 8) SC_FLAG[idx] = 0u;
}

// ---------------- mma conv (unchanged, M128 tile) ----------------
__global__ __launch_bounds__(256, 2)
void k_mmconv(int ksz, int tapBase, int ocBase, const float* __restrict__ bias, int N) {
    extern __shared__ char smem[];
    uint32_t sb = smem_u32(smem);
    int tid = threadIdx.x, lane = tid & 31, wid = tid >> 5;
    int wm = wid & 3, wn = wid >> 2;
    int m0 = blockIdx.x * 128, n0 = blockIdx.y * 128;
    int pad = ksz >> 1;
    int nblk = ksz * 34;
    float acc[2][8][4] = {};

    auto load_blk = [&](int i) {
        int buf = i & 1;
        int p = i / 34, kb = i - p * 34;
        int sh = p - pad;
        uint32_t bb = sb + buf * BUFB;
        const __nv_bfloat16* wth = WTBh + (size_t)(tapBase + p) * 256 * KPADX;
        const __nv_bfloat16* wtl = WTBl + (size_t)(tapBase + p) * 256 * KPADX;
        ldp(bb,             XBh, KPADX, m0 + sh, N,   kb * 32, tid);
        ldp(bb + PLANE,     XBl, KPADX, m0 + sh, N,   kb * 32, tid);
        ldp(bb + 2 * PLANE, wth, KPADX, n0,      256, kb * 32, tid);
        ldp(bb + 3 * PLANE, wtl, KPADX, n0,      256, kb * 32, tid);
        CP_COMMIT();
    };

    load_blk(0);
    for (int i = 0; i < nblk; ++i) {
        if (i + 1 < nblk) { load_blk(i + 1); CP_WAIT1(); } else { CP_WAIT0(); }
        __syncthreads();
        wcompute(sb + (i & 1) * BUFB, lane, wm, wn, acc);
        __syncthreads();
    }

#pragma unroll
    for (int mt = 0; mt < 2; ++mt)
#pragma unroll
        for (int nt = 0; nt < 8; ++nt) {
            int col = n0 + wn * 64 + nt * 8 + (lane & 3) * 2;
            float b0 = bias[col], b1 = bias[col + 1];
            int r0 = m0 + wm * 32 + mt * 16 + (lane >> 2);
#pragma unroll
            for (int hh = 0; hh < 2; ++hh) {
                int m = r0 + hh * 8;
                if (m < N) {
                    float v0 = acc[mt][nt][hh * 2]     + b0;
                    float v1 = acc[mt][nt][hh * 2 + 1] + b1;
                    v0 = (v0 >= 0.f) ? v0 : 0.01f * v0;
                    v1 = (v1 >= 0.f) ? v1 : 0.01f * v1;
                    SC_FEAT[(size_t)m * FDIM + ocBase + col]     = v0;
                    SC_FEAT[(size_t)m * FDIM + ocBase + col + 1] = v1;
                }
            }
        }
}

// ---------------- gate GEMM M256: SC_G = A1@B1^T [+ A2(shift)@B2^T] + b1 + b2 ----------------
__global__ __launch_bounds__(256, 1)
void k_mmgate(int aSel, int wSlot, int pass2, int wSlot2, int shift2,
              const float* __restrict__ b1, const float* __restrict__ b2, int N) {
    extern __shared__ char smem[];
    uint32_t sb = smem_u32(smem);
    int tid = threadIdx.x, lane = tid & 31, wid = tid >> 5;
    int wm = wid & 3, wn = wid >> 2;
    int m0 = blockIdx.x * 256, n0 = blockIdx.y * 128;
    int nblk = pass2 ? 48 : 24;
    float acc[4][8][4] = {};

    auto load_blk = [&](int i) {
        int buf = i & 1;
        int p = i / 24, kb = i - p * 24;
        const __nv_bfloat16 *ah, *al, *bh, *bl;
        int sh;
        if (p == 0) {
            ah = aSel ? FBh : PBh; al = aSel ? FBl : PBl;
            bh = WGBh + (size_t)wSlot * G4 * FDIM;
            bl = WGBl + (size_t)wSlot * G4 * FDIM;
            sh = 0;
        } else {
            ah = HBh; al = HBl;
            bh = WGBh + (size_t)wSlot2 * G4 * FDIM;
            bl = WGBl + (size_t)wSlot2 * G4 * FDIM;
            sh = shift2;
        }
        uint32_t bb = sb + buf * BUF256;
        ldp256(bb,              ah, FDIM, m0 + sh, N,  kb * 32, tid);
        ldp256(bb + APL256,     al, FDIM, m0 + sh, N,  kb * 32, tid);
        ldp(bb + 2 * APL256,         bh, FDIM, n0, G4, kb * 32, tid);
        ldp(bb + 2 * APL256 + PLANE, bl, FDIM, n0, G4, kb * 32, tid);
        CP_COMMIT();
    };

    load_blk(0);
    for (int i = 0; i < nblk; ++i) {
        if (i + 1 < nblk) { load_blk(i + 1); CP_WAIT1(); } else { CP_WAIT0(); }
        __syncthreads();
        wcompute256(sb + (i & 1) * BUF256, lane, wm, wn, acc);
        __syncthreads();
    }

#pragma unroll
    for (int mt = 0; mt < 4; ++mt)
#pragma unroll
        for (int nt = 0; nt < 8; ++nt) {
            int g = n0 + wn * 64 + nt * 8 + (lane & 3) * 2;
            float bv0 = b1[g] + b2[g];
            float bv1 = b1[g + 1] + b2[g + 1];
            int r0 = m0 + wm * 64 + mt * 16 + (lane >> 2);
#pragma unroll
            for (int hh = 0; hh < 2; ++hh) {
                int m = r0 + hh * 8;
                if (m < N) {
                    SC_G[(size_t)m * G4 + g]     = acc[mt][nt][hh * 2]     + bv0;
                    SC_G[(size_t)m * G4 + g + 1] = acc[mt][nt][hh * 2 + 1] + bv1;
                }
            }
        }
}

// ---------------- fused: FEAT -> FB planes; maxpool -> PB planes ----------------
__global__ void k_postconv(int N) {
    long long idx = (long long)blockIdx.x * blockDim.x + threadIdx.x;
    long long tot = (long long)N * FDIM;
    if (idx >= tot) return;
    int n = (int)(idx / FDIM), ch = (int)(idx % FDIM);
    float f = SC_FEAT[idx];
    __nv_bfloat16 fh = __float2bfloat16(f);
    FBh[idx] = fh;
    FBl[idx] = __float2bfloat16(f - __bfloat162float(fh));
    int ksz = 3 + 2 * (ch >> 8);
    int p = ksz >> 1;
    float m = f;
    for (int d = -p; d <= p; ++d) {
        int nn = n + d;
        if (d != 0 && nn >= 0 && nn < N) m = fmaxf(m, SC_FEAT[(long long)nn * FDIM + ch]);
    }
    __nv_bfloat16 mh = __float2bfloat16(m);
    PBh[idx] = mh;
    PBl[idx] = __float2bfloat16(m - __bfloat162float(mh));
}

// ---------------- persistent chunked-LSTM scan v5b (R13, unchanged) ----------------
#define HROW 776
#define HPL  (16 * HROW)
#define SCAN_SMEM (2 * HPL * 2 + 12 * 128 * 4)

__global__ __launch_bounds__(384, 1)
void k_scan(int N, int nChunks) {
    extern __shared__ char sms[];
    __nv_bfloat16* hs = (__nv_bfloat16*)sms;
    float* cst = (float*)(sms + 2 * HPL * 2);
    uint32_t hs_addr = smem_u32(hs);
    int t = threadIdx.x, b = blockIdx.x;
    int lane = t & 31, wid = t >> 5;
    int wn = wid % 3, wk = wid / 3;
    int j = t & 15;
    int hl = t >> 4;
    int h_idx = b * 6 + hl;

    uint32_t wb0h[12], wb1h[12], wb0l[12], wb1l[12];
    {
        int n = wn * 8 + (lane >> 2);
        int gr = (n / 6) * FDIM + b * 6 + (n % 6);
        const __nv_bfloat16* Wh = WGBh + (size_t)1 * G4 * FDIM + (size_t)gr * FDIM;
        const __nv_bfloat16* Wl = WGBl + (size_t)1 * G4 * FDIM + (size_t)gr * FDIM;
#pragma unroll
        for (int c = 0; c < 12; ++c) {
            int kb = (wk * 12 + c) * 16 + (lane & 3) * 2;
            wb0h[c] = *(const uint32_t*)(Wh + kb);
            wb1h[c] = *(const uint32_t*)(Wh + kb + 8);
            wb0l[c] = *(const uint32_t*)(Wl + kb);
            wb1l[c] = *(const uint32_t*)(Wl + kb + 8);
        }
    }
    float c_reg = 0.f;

    for (int s = 0; s < nChunks; ++s) {
        int pos = s * 16 + j;
        float gpre[4] = {0.f, 0.f, 0.f, 0.f};
        if (t < 96 && pos < N) {
#pragma unroll
            for (int g = 0; g < 4; ++g)
                gpre[g] = __ldg(&SC_G[(size_t)pos * G4 + g * FDIM + h_idx]);
        }
        if (s > 0 && t < 128) {
            while (*(volatile unsigned*)&SC_FLAG[t * 8] < (unsigned)s) __nanosleep(32);
        }
        __syncthreads();
        __threadfence();

        float C[4] = {0.f, 0.f, 0.f, 0.f};
        if (s > 0) {
            int srow = (s - 1) * 16;
#pragma unroll
            for (int i = 0; i < 8; ++i) {
                int c = t + i * 384;
                int plane = c / 1536;
                int rem = c - plane * 1536;
                int row = rem / 96, kk = rem - row * 96;
                const __nv_bfloat16* srcp = plane ? HBl : HBh;
                uint4 v = __ldcg((const uint4*)(srcp + (size_t)(srow + row) * FDIM + kk * 8));
                *(uint4*)(hs + plane * HPL + row * HROW + kk * 8) = v;
            }
            __syncthreads();

            uint32_t abase = hs_addr + (lane & 15) * (HROW * 2) + (lane >> 4) * 16;
#pragma unroll
            for (int c = 0; c < 12; ++c) {
                uint32_t koff = (uint32_t)((wk * 12 + c) * 32);
                uint32_t ah[4], al[4];
                ldsm4(ah, abase + koff);
                ldsm4(al, abase + (uint32_t)(HPL * 2) + koff);
                mma16816(C, ah, wb0h[c], wb1h[c]);
                mma16816(C, ah, wb0l[c], wb1l[c]);
                mma16816(C, al, wb0h[c], wb1h[c]);
            }
        }
        *(float4*)&cst[wid * 128 + lane * 4] = make_float4(C[0], C[1], C[2], C[3]);
        __syncthreads();

        if (t < 96 && pos < N) {
            float pre[4];
#pragma unroll
            for (int g = 0; g < 4; ++g) {
                int r = g * 6 + hl;
                int wnn = r >> 3, cl = r & 7;
                int ln = (j & 7) * 4 + (cl >> 1);
                int rg = (cl & 1) + ((j >> 3) << 1);
                float sgd = gpre[g];
#pragma unroll
                for (int wq = 0; wq < 4; ++wq)
                    sgd += cst[(wq * 3 + wnn) * 128 + ln * 4 + rg];
                pre[g] = sgd;
            }
            float c2 = sigm(pre[1]) * c_reg + sigm(pre[0]) * tanhf(pre[2]);
            float h2 = sigm(pre[3]) * tanhf(c2);
            c_reg = c2;
            size_t o = (size_t)pos * FDIM + h_idx;
            SC_CS[o] = c2;
            __nv_bfloat16 hh = __float2bfloat16(h2);
            HBh[o] = hh;
            HBl[o] = __float2bfloat16(h2 - __bfloat162float(hh));
        }

        __threadfence();
        __syncthreads();
        if (t == 0) atomicExch(&SC_FLAG[b * 8], (unsigned)(s + 1));
    }
}

// ---------------- final LSTM-cell gate fuse ----------------
__global__ void k_final(float* __restrict__ out, int N, int shift, int outOff) {
    long long idx = (long long)blockIdx.x * blockDim.x + threadIdx.x;
    long long tot = (long long)N * FDIM;
    if (idx >= tot) return;
    int n = (int)(idx / FDIM), h = (int)(idx % FDIM);
    int ns = n + shift;
    float cin = (ns >= 0 && ns < N) ? SC_CS[(long long)ns * FDIM + h] : 0.f;
    const float* g = SC_G + (long long)n * G4;
    float gi = g[h], gf = g[FDIM + h], gg = g[2 * FDIM + h], go = g[3 * FDIM + h];
    float c2 = sigm(gf) * cin + sigm(gi) * tanhf(gg);
    out[(long long)n * 1536 + outOff + h] = sigm(go) * tanhf(c2);
}

// ---------------- launch ----------------
extern "C" void kernel_launch(void* const* d_in, const int* in_sizes, int n_in,
                              void* d_out, int out_size) {
    const float* x    = (const float*)d_in[0];
    const int*   dl   = (const int*)  d_in[1];
    const float* cw0  = (const float*)d_in[2];  const float* cb0 = (const float*)d_in[3];
    const float* cw1  = (const float*)d_in[4];  const float* cb1 = (const float*)d_in[5];
    const float* cw2  = (const float*)d_in[6];  const float* cb2 = (const float*)d_in[7];
    const float* Wih  = (const float*)d_in[8];  const float* Whh  = (const float*)d_in[9];
    const float* bih  = (const float*)d_in[10]; const float* bhh  = (const float*)d_in[11];
    const float* WihR = (const float*)d_in[12]; const float* WhhR = (const float*)d_in[13];
    const float* bihR = (const float*)d_in[14]; const float* bhhR = (const float*)d_in[15];
    float* out = (float*)d_out;

    int ndocs = in_sizes[1];
    int N = out_size / 1536;
    if (N > MAXN) N = MAXN;
    int nChunks = (N + 15) / 16;

    cudaFuncSetAttribute(k_mmconv, cudaFuncAttributeMaxDynamicSharedMemorySize, SMEM_MMA);
    cudaFuncSetAttribute(k_mmgate, cudaFuncAttributeMaxDynamicSharedMemorySize, SMEM_G256);
    cudaFuncSetAttribute(k_scan,   cudaFuncAttributeMaxDynamicSharedMemorySize, SCAN_SMEM);

    // 0: PE + posidx + conv weight transpose
    k_prep<<<(15 * 256 * D_IN + 255) / 256, 256>>>(dl, ndocs, N, cw0, cw1, cw2);
    // 1: x + PE -> XB planes
    {
        long long tot = (long long)N * KPADX;
        k_addpe_cvt<<<(int)((tot + 255) / 256), 256>>>(x, N);
    }
    // 2: all weight conversions + flag reset
    k_wcvt<<<(int)((4LL * G4 * FDIM + 255) / 256), 256>>>(Wih, Whh, WihR, WhhR);

    int mt = (N + 127) / 128;
    dim3 cg(mt, 2);
    // 3-5: convs
    k_mmconv<<<cg, 256, SMEM_MMA>>>(7, 8, 512, cb2, N);
    k_mmconv<<<cg, 256, SMEM_MMA>>>(5, 3, 256, cb1, N);
    k_mmconv<<<cg, 256, SMEM_MMA>>>(3, 0, 0,   cb0, N);

    // 6: pool + FB/PB planes
    {
        long long tot = (long long)N * FDIM;
        k_postconv<<<(int)((tot + 255) / 256), 256>>>(N);
    }

    int mt2 = (N + 255) / 256;
    dim3 gg(mt2, G4 / 128);
    // 7: gx = pool @ Wih^T + b_ih + b_hh
    k_mmgate<<<gg, 256, SMEM_G256>>>(0, 0, 0, 0, 0, bih, bhh, N);
    // 8: scan
    k_scan<<<128, 384, SCAN_SMEM>>>(N, nChunks);

    // 9-10: forward final cell
    k_mmgate<<<gg, 256, SMEM_G256>>>(1, 0, 1, 1, -9, bih, bhh, N);
    {
        long long tot = (long long)N * FDIM;
        k_final<<<(int)((tot + 255) / 256), 256>>>(out, N, -9, 0);
    }
    // 11-12: reverse final cell
    k_mmgate<<<gg, 256, SMEM_G256>>>(1, 2, 1, 3, 9, bihR, bhhR, N);
    {
        long long tot = (long long)N * FDIM;
        k_final<<<(int)((tot + 255) / 256), 256>>>(out, N, 9, 768);
    }
}

// round 16
// speedup vs baseline: 1.0736x; 1.0736x over previous
#include <cuda_runtime.h>
#include <cuda_bf16.h>
#include <math.h>
#include <stdint.h>

#define MAXN   25600
#define D_IN   1068
#define KPADX  1088
#define FDIM   768
#define G4     3072
#define NPE    200
#define MAXDOC 256

typedef unsigned long long ull;

// ---------------- scratch (static device arrays; no allocations) ----------------
__device__ float SC_PE  [NPE * D_IN];
__device__ int   SC_POS [MAXN];
__device__ float SC_WT  [15 * 256 * D_IN];            // taps: 0..2 (k3), 3..7 (k5), 8..14 (k7)
__device__ float SC_FEAT[(size_t)MAXN * FDIM];
__device__ float SC_G   [(size_t)MAXN * G4];
__device__ float SC_G2  [(size_t)MAXN * G4];
__device__ float SC_CS  [(size_t)MAXN * FDIM];
__device__ unsigned SC_FLAG[128 * 8];                 // padded per-block barrier flags

// bf16 split planes (hi + lo), 16B aligned for cp.async
__device__ __align__(16) __nv_bfloat16 XBh[(size_t)MAXN * KPADX], XBl[(size_t)MAXN * KPADX];
__device__ __align__(16) __nv_bfloat16 WTBh[(size_t)3840 * KPADX], WTBl[(size_t)3840 * KPADX];
__device__ __align__(16) __nv_bfloat16 FBh[(size_t)MAXN * FDIM], FBl[(size_t)MAXN * FDIM];
__device__ __align__(16) __nv_bfloat16 PBh[(size_t)MAXN * FDIM], PBl[(size_t)MAXN * FDIM];
__device__ __align__(16) __nv_bfloat16 HBh[(size_t)MAXN * FDIM], HBl[(size_t)MAXN * FDIM];
__device__ __align__(16) __nv_bfloat16 WGBh[(size_t)4 * G4 * FDIM], WGBl[(size_t)4 * G4 * FDIM];

__device__ __forceinline__ float sigm(float x) { return 1.0f / (1.0f + expf(-x)); }

// ---- mma.sync / ldmatrix / cp.async (base PTX, compute_103-safe) ----
__device__ __forceinline__ uint32_t smem_u32(const void* p) {
    uint32_t a;
    asm("{ .reg .u64 t; cvta.to.shared.u64 t, %1; cvt.u32.u64 %0, t; }" : "=r"(a) : "l"(p));
    return a;
}
__device__ __forceinline__ void ldsm4(uint32_t* r, uint32_t addr) {
    asm volatile("ldmatrix.sync.aligned.m8n8.x4.shared.b16 {%0,%1,%2,%3}, [%4];"
        : "=r"(r[0]), "=r"(r[1]), "=r"(r[2]), "=r"(r[3]) : "r"(addr));
}
__device__ __forceinline__ void mma16816(float* c, const uint32_t* a, uint32_t b0, uint32_t b1) {
    asm volatile("mma.sync.aligned.m16n8k16.row.col.f32.bf16.bf16.f32 "
        "{%0,%1,%2,%3}, {%4,%5,%6,%7}, {%8,%9}, {%0,%1,%2,%3};"
        : "+f"(c[0]), "+f"(c[1]), "+f"(c[2]), "+f"(c[3])
        : "r"(a[0]), "r"(a[1]), "r"(a[2]), "r"(a[3]), "r"(b0), "r"(b1));
}
__device__ __forceinline__ void cpa16(uint32_t dst, const void* src, int valid) {
    asm volatile("cp.async.cg.shared.global [%0], [%1], 16, %2;"
        :: "r"(dst), "l"(src), "r"(valid ? 16 : 0) : "memory");
}
#define CP_COMMIT() asm volatile("cp.async.commit_group;" ::: "memory")
#define CP_WAIT1()  asm volatile("cp.async.wait_group 1;" ::: "memory")
#define CP_WAIT0()  asm volatile("cp.async.wait_group 0;" ::: "memory")

#define RS     80
#define PLANE  10240
#define BUFB   40960
#define SMEM_MMA (2 * BUFB)

// load one 128x32 bf16 plane into smem (2 chunks of 16B per thread)
__device__ __forceinline__ void ldp(uint32_t sdst, const __nv_bfloat16* src, int ldk,
                                    int rowBase, int rowLim, int kcol, int tid) {
#pragma unroll
    for (int it = 0; it < 2; ++it) {
        int ch = tid + it * 256;
        int row = ch >> 2, c = ch & 3;
        int r = rowBase + row;
        int v = (r >= 0 && r < rowLim);
        const void* s = src + ((size_t)(v ? r : 0) * ldk + kcol + c * 8);
        cpa16(sdst + row * RS + c * 16, s, v);
    }
}

// per-warp compute on one 32-K block (M128 tile): 3 split combos, acc[2][8][4]
__device__ __forceinline__ void wcompute(uint32_t sbuf, int lane, int wm, int wn,
                                         float acc[2][8][4]) {
    int arow = wm * 32 + (lane & 15);
    int brow = wn * 64 + (lane & 7) + ((lane >> 4) << 3);
#pragma unroll
    for (int kh = 0; kh < 2; ++kh) {
        int acol = kh * 16 + ((lane >> 4) << 3);
        int bcol = kh * 16 + (((lane >> 3) & 1) << 3);
        uint32_t ah[2][4], al[2][4];
#pragma unroll
        for (int mt = 0; mt < 2; ++mt) {
            uint32_t ad = sbuf + (arow + mt * 16) * RS + acol * 2;
            ldsm4(ah[mt], ad);
            ldsm4(al[mt], ad + PLANE);
        }
#pragma unroll
        for (int g = 0; g < 4; ++g) {
            uint32_t bh[4], bl[4];
            uint32_t bd = sbuf + 2 * PLANE + (brow + g * 16) * RS + bcol * 2;
            ldsm4(bh, bd);
            ldsm4(bl, bd + PLANE);
#pragma unroll
            for (int mt = 0; mt < 2; ++mt)
#pragma unroll
                for (int sub = 0; sub < 2; ++sub) {
                    int nt = g * 2 + sub;
                    mma16816(acc[mt][nt], ah[mt], bh[sub * 2], bh[sub * 2 + 1]);
                    mma16816(acc[mt][nt], ah[mt], bl[sub * 2], bl[sub * 2 + 1]);
                    mma16816(acc[mt][nt], al[mt], bh[sub * 2], bh[sub * 2 + 1]);
                }
        }
    }
}

// ---------------- fused prep: PE + posidx + conv weight transpose ----------------
__global__ void k_prep(const int* __restrict__ dl, int ndocs, int N,
                       const float* __restrict__ w0, const float* __restrict__ w1,
                       const float* __restrict__ w2) {
    int idx = blockIdx.x * blockDim.x + threadIdx.x;
    if (idx < NPE * D_IN) {
        int pos = idx / D_IN, ch = idx % D_IN;
        int i = ch >> 1;
        float e = (2.0f * (float)i) / (float)D_IN;
        float ang = (float)pos / powf(10000.0f, e);
        SC_PE[idx] = (ch & 1) ? cosf(ang) : sinf(ang);
    }
    const int per = 256 * D_IN;
    if (idx < 15 * per) {
        int t  = idx / per;
        int r  = idx - t * per;
        int oc = r / D_IN;
        int c  = r - oc * D_IN;
        const float* w; int ksz, tl;
        if (t < 3)      { w = w0; ksz = 3; tl = t; }
        else if (t < 8) { w = w1; ksz = 5; tl = t - 3; }
        else            { w = w2; ksz = 7; tl = t - 8; }
        SC_WT[idx] = w[((size_t)oc * D_IN + c) * ksz + tl];
    }
    if (blockIdx.x == 0) {
        __shared__ int off[MAXDOC + 1];
        if (threadIdx.x == 0) {
            int s = 0;
            for (int d = 0; d < ndocs; ++d) { off[d] = s; s += dl[d]; }
            off[ndocs] = s;
        }
        __syncthreads();
        for (int n = threadIdx.x; n < N; n += blockDim.x) {
            int lo = 0, hi = ndocs;
            while (hi - lo > 1) { int mid = (lo + hi) >> 1; if (off[mid] <= n) lo = mid; else hi = mid; }
            SC_POS[n] = n - off[lo];
        }
    }
}

// ---------------- fused: x + PE -> bf16 hi/lo planes ----------------
__global__ void k_addpe_cvt(const float* __restrict__ x, int N) {
    long long idx = (long long)blockIdx.x * blockDim.x + threadIdx.x;
    long long tot = (long long)N * KPADX;
    if (idx >= tot) return;
    int n = (int)(idx / KPADX), k = (int)(idx % KPADX);
    float v = 0.f;
    if (k < D_IN) v = x[(size_t)n * D_IN + k] + SC_PE[SC_POS[n] * D_IN + k];
    __nv_bfloat16 h = __float2bfloat16(v);
    XBh[idx] = h;
    XBl[idx] = __float2bfloat16(v - __bfloat162float(h));
}

// ---------------- fused weight conversions: WT planes + gate weight planes + reset ----------------
__global__ void k_wcvt(const float* __restrict__ s0, const float* __restrict__ s1,
                       const float* __restrict__ s2, const float* __restrict__ s3) {
    long long idx = (long long)blockIdx.x * blockDim.x + threadIdx.x;
    if (idx < (long long)3840 * KPADX) {
        int r = (int)(idx / KPADX), k = (int)(idx % KPADX);
        float v = (k < D_IN) ? SC_WT[(size_t)r * D_IN + k] : 0.f;
        __nv_bfloat16 h = __float2bfloat16(v);
        WTBh[idx] = h;
        WTBl[idx] = __float2bfloat16(v - __bfloat162float(h));
    }
    const long long per = (long long)G4 * FDIM;
    if (idx < 4 * per) {
        int slot = (int)(idx / per);
        long long r = idx - (long long)slot * per;
        const float* s = (slot == 0) ? s0 : (slot == 1) ? s1 : (slot == 2) ? s2 : s3;
        float v = s[r];
        __nv_bfloat16 h = __float2bfloat16(v);
        WGBh[idx] = h;
        WGBl[idx] = __float2bfloat16(v - __bfloat162float(h));
    }
    if (idx < 128 * 8) SC_FLAG[idx] = 0u;
}

// ---------------- merged mma conv: all 3 convs in one launch, grid y in 0..5 ----------------
// y: 0-1 -> k7 (ocBase 512), 2-3 -> k5 (256), 4-5 -> k3 (0); ocHalf = y & 1.
__global__ __launch_bounds__(256, 2)
void k_mmconv_all(const float* __restrict__ cb3, const float* __restrict__ cb5,
                  const float* __restrict__ cb7, int N) {
    extern __shared__ char smem[];
    uint32_t sb = smem_u32(smem);
    int tid = threadIdx.x, lane = tid & 31, wid = tid >> 5;
    int wm = wid & 3, wn = wid >> 2;
    int y = blockIdx.y;
    int conv = y >> 1;                    // 0:k7, 1:k5, 2:k3
    int ksz     = (conv == 0) ? 7 : (conv == 1) ? 5 : 3;
    int tapBase = (conv == 0) ? 8 : (conv == 1) ? 3 : 0;
    int ocBase  = (conv == 0) ? 512 : (conv == 1) ? 256 : 0;
    const float* bias = (conv == 0) ? cb7 : (conv == 1) ? cb5 : cb3;
    int m0 = blockIdx.x * 128, n0 = (y & 1) * 128;
    int pad = ksz >> 1;
    int nblk = ksz * 34;
    float acc[2][8][4] = {};

    auto load_blk = [&](int i) {
        int buf = i & 1;
        int p = i / 34, kb = i - p * 34;
        int sh = p - pad;
        uint32_t bb = sb + buf * BUFB;
        const __nv_bfloat16* wth = WTBh + (size_t)(tapBase + p) * 256 * KPADX;
        const __nv_bfloat16* wtl = WTBl + (size_t)(tapBase + p) * 256 * KPADX;
        ldp(bb,             XBh, KPADX, m0 + sh, N,   kb * 32, tid);
        ldp(bb + PLANE,     XBl, KPADX, m0 + sh, N,   kb * 32, tid);
        ldp(bb + 2 * PLANE, wth, KPADX, n0,      256, kb * 32, tid);
        ldp(bb + 3 * PLANE, wtl, KPADX, n0,      256, kb * 32, tid);
        CP_COMMIT();
    };

    load_blk(0);
    for (int i = 0; i < nblk; ++i) {
        if (i + 1 < nblk) { load_blk(i + 1); CP_WAIT1(); } else { CP_WAIT0(); }
        __syncthreads();
        wcompute(sb + (i & 1) * BUFB, lane, wm, wn, acc);
        __syncthreads();
    }

#pragma unroll
    for (int mt = 0; mt < 2; ++mt)
#pragma unroll
        for (int nt = 0; nt < 8; ++nt) {
            int col = n0 + wn * 64 + nt * 8 + (lane & 3) * 2;
            float b0 = bias[col], b1 = bias[col + 1];
            int r0 = m0 + wm * 32 + mt * 16 + (lane >> 2);
#pragma unroll
            for (int hh = 0; hh < 2; ++hh) {
                int m = r0 + hh * 8;
                if (m < N) {
                    float v0 = acc[mt][nt][hh * 2]     + b0;
                    float v1 = acc[mt][nt][hh * 2 + 1] + b1;
                    v0 = (v0 >= 0.f) ? v0 : 0.01f * v0;
                    v1 = (v1 >= 0.f) ? v1 : 0.01f * v1;
                    SC_FEAT[(size_t)m * FDIM + ocBase + col]     = v0;
                    SC_FEAT[(size_t)m * FDIM + ocBase + col + 1] = v1;
                }
            }
        }
}

// ---------------- gx gate GEMM (R13 form, single pass): SC_G = pool@Wih^T + b ----------------
__global__ __launch_bounds__(256, 2)
void k_mmgate(const float* __restrict__ b1, const float* __restrict__ b2, int N) {
    extern __shared__ char smem[];
    uint32_t sb = smem_u32(smem);
    int tid = threadIdx.x, lane = tid & 31, wid = tid >> 5;
    int wm = wid & 3, wn = wid >> 2;
    int m0 = blockIdx.x * 128, n0 = blockIdx.y * 128;
    float acc[2][8][4] = {};

    auto load_blk = [&](int i) {
        int buf = i & 1;
        uint32_t bb = sb + buf * BUFB;
        ldp(bb,             PBh, FDIM, m0, N,  i * 32, tid);
        ldp(bb + PLANE,     PBl, FDIM, m0, N,  i * 32, tid);
        ldp(bb + 2 * PLANE, WGBh, FDIM, n0, G4, i * 32, tid);
        ldp(bb + 3 * PLANE, WGBl, FDIM, n0, G4, i * 32, tid);
        CP_COMMIT();
    };

    load_blk(0);
    for (int i = 0; i < 24; ++i) {
        if (i + 1 < 24) { load_blk(i + 1); CP_WAIT1(); } else { CP_WAIT0(); }
        __syncthreads();
        wcompute(sb + (i & 1) * BUFB, lane, wm, wn, acc);
        __syncthreads();
    }

#pragma unroll
    for (int mt = 0; mt < 2; ++mt)
#pragma unroll
        for (int nt = 0; nt < 8; ++nt) {
            int g = n0 + wn * 64 + nt * 8 + (lane & 3) * 2;
            float bv0 = b1[g] + b2[g];
            float bv1 = b1[g + 1] + b2[g + 1];
            int r0 = m0 + wm * 32 + mt * 16 + (lane >> 2);
#pragma unroll
            for (int hh = 0; hh < 2; ++hh) {
                int m = r0 + hh * 8;
                if (m < N) {
                    SC_G[(size_t)m * G4 + g]     = acc[mt][nt][hh * 2]     + bv0;
                    SC_G[(size_t)m * G4 + g + 1] = acc[mt][nt][hh * 2 + 1] + bv1;
                }
            }
        }
}

// ---------------- merged final gate GEMMs: grid z = 0 (fwd->SC_G) / 1 (rev->SC_G2) ----------------
__global__ __launch_bounds__(256, 2)
void k_mmfinal(const float* __restrict__ bih,  const float* __restrict__ bhh,
               const float* __restrict__ bihR, const float* __restrict__ bhhR, int N) {
    extern __shared__ char smem[];
    uint32_t sb = smem_u32(smem);
    int tid = threadIdx.x, lane = tid & 31, wid = tid >> 5;
    int wm = wid & 3, wn = wid >> 2;
    int m0 = blockIdx.x * 128, n0 = blockIdx.y * 128;
    int z = blockIdx.z;
    int wSlot  = z ? 2 : 0;
    int wSlot2 = z ? 3 : 1;
    int shift2 = z ? 9 : -9;
    const float* b1 = z ? bihR : bih;
    const float* b2 = z ? bhhR : bhh;
    float* dst = z ? SC_G2 : SC_G;
    float acc[2][8][4] = {};

    auto load_blk = [&](int i) {
        int buf = i & 1;
        int p = i / 24, kb = i - p * 24;
        const __nv_bfloat16 *ah, *al, *bh, *bl;
        int sh;
        if (p == 0) {
            ah = FBh; al = FBl;
            bh = WGBh + (size_t)wSlot * G4 * FDIM;
            bl = WGBl + (size_t)wSlot * G4 * FDIM;
            sh = 0;
        } else {
            ah = HBh; al = HBl;
            bh = WGBh + (size_t)wSlot2 * G4 * FDIM;
            bl = WGBl + (size_t)wSlot2 * G4 * FDIM;
            sh = shift2;
        }
        uint32_t bb = sb + buf * BUFB;
        ldp(bb,             ah, FDIM, m0 + sh, N,  kb * 32, tid);
        ldp(bb + PLANE,     al, FDIM, m0 + sh, N,  kb * 32, tid);
        ldp(bb + 2 * PLANE, bh, FDIM, n0,      G4, kb * 32, tid);
        ldp(bb + 3 * PLANE, bl, FDIM, n0,      G4, kb * 32, tid);
        CP_COMMIT();
    };

    load_blk(0);
    for (int i = 0; i < 48; ++i) {
        if (i + 1 < 48) { load_blk(i + 1); CP_WAIT1(); } else { CP_WAIT0(); }
        __syncthreads();
        wcompute(sb + (i & 1) * BUFB, lane, wm, wn, acc);
        __syncthreads();
    }

#pragma unroll
    for (int mt = 0; mt < 2; ++mt)
#pragma unroll
        for (int nt = 0; nt < 8; ++nt) {
            int g = n0 + wn * 64 + nt * 8 + (lane & 3) * 2;
            float bv0 = b1[g] + b2[g];
            float bv1 = b1[g + 1] + b2[g + 1];
            int r0 = m0 + wm * 32 + mt * 16 + (lane >> 2);
#pragma unroll
            for (int hh = 0; hh < 2; ++hh) {
                int m = r0 + hh * 8;
                if (m < N) {
                    dst[(size_t)m * G4 + g]     = acc[mt][nt][hh * 2]     + bv0;
                    dst[(size_t)m * G4 + g + 1] = acc[mt][nt][hh * 2 + 1] + bv1;
                }
            }
        }
}

// ---------------- fused: FEAT -> FB planes; maxpool -> PB planes ----------------
__global__ void k_postconv(int N) {
    long long idx = (long long)blockIdx.x * blockDim.x + threadIdx.x;
    long long tot = (long long)N * FDIM;
    if (idx >= tot) return;
    int n = (int)(idx / FDIM), ch = (int)(idx % FDIM);
    float f = SC_FEAT[idx];
    __nv_bfloat16 fh = __float2bfloat16(f);
    FBh[idx] = fh;
    FBl[idx] = __float2bfloat16(f - __bfloat162float(fh));
    int ksz = 3 + 2 * (ch >> 8);
    int p = ksz >> 1;
    float m = f;
    for (int d = -p; d <= p; ++d) {
        int nn = n + d;
        if (d != 0 && nn >= 0 && nn < N) m = fmaxf(m, SC_FEAT[(long long)nn * FDIM + ch]);
    }
    __nv_bfloat16 mh = __float2bfloat16(m);
    PBh[idx] = mh;
    PBl[idx] = __float2bfloat16(m - __bfloat162float(mh));
}

// ---------------- persistent chunked-LSTM scan (R13, unchanged) ----------------
#define HROW 776
#define HPL  (16 * HROW)
#define SCAN_SMEM (2 * HPL * 2 + 12 * 128 * 4)

__global__ __launch_bounds__(384, 1)
void k_scan(int N, int nChunks) {
    extern __shared__ char sms[];
    __nv_bfloat16* hs = (__nv_bfloat16*)sms;
    float* cst = (float*)(sms + 2 * HPL * 2);
    uint32_t hs_addr = smem_u32(hs);
    int t = threadIdx.x, b = blockIdx.x;
    int lane = t & 31, wid = t >> 5;
    int wn = wid % 3, wk = wid / 3;
    int j = t & 15;
    int hl = t >> 4;
    int h_idx = b * 6 + hl;

    uint32_t wb0h[12], wb1h[12], wb0l[12], wb1l[12];
    {
        int n = wn * 8 + (lane >> 2);
        int gr = (n / 6) * FDIM + b * 6 + (n % 6);
        const __nv_bfloat16* Wh = WGBh + (size_t)1 * G4 * FDIM + (size_t)gr * FDIM;
        const __nv_bfloat16* Wl = WGBl + (size_t)1 * G4 * FDIM + (size_t)gr * FDIM;
#pragma unroll
        for (int c = 0; c < 12; ++c) {
            int kb = (wk * 12 + c) * 16 + (lane & 3) * 2;
            wb0h[c] = *(const uint32_t*)(Wh + kb);
            wb1h[c] = *(const uint32_t*)(Wh + kb + 8);
            wb0l[c] = *(const uint32_t*)(Wl + kb);
            wb1l[c] = *(const uint32_t*)(Wl + kb + 8);
        }
    }
    float c_reg = 0.f;

    for (int s = 0; s < nChunks; ++s) {
        int pos = s * 16 + j;
        float gpre[4] = {0.f, 0.f, 0.f, 0.f};
        if (t < 96 && pos < N) {
#pragma unroll
            for (int g = 0; g < 4; ++g)
                gpre[g] = __ldg(&SC_G[(size_t)pos * G4 + g * FDIM + h_idx]);
        }
        if (s > 0 && t < 128) {
            while (*(volatile unsigned*)&SC_FLAG[t * 8] < (unsigned)s) __nanosleep(32);
        }
        __syncthreads();
        __threadfence();

        float C[4] = {0.f, 0.f, 0.f, 0.f};
        if (s > 0) {
            int srow = (s - 1) * 16;
#pragma unroll
            for (int i = 0; i < 8; ++i) {
                int c = t + i * 384;
                int plane = c / 1536;
                int rem = c - plane * 1536;
                int row = rem / 96, kk = rem - row * 96;
                const __nv_bfloat16* srcp = plane ? HBl : HBh;
                uint4 v = __ldcg((const uint4*)(srcp + (size_t)(srow + row) * FDIM + kk * 8));
                *(uint4*)(hs + plane * HPL + row * HROW + kk * 8) = v;
            }
            __syncthreads();

            uint32_t abase = hs_addr + (lane & 15) * (HROW * 2) + (lane >> 4) * 16;
#pragma unroll
            for (int c = 0; c < 12; ++c) {
                uint32_t koff = (uint32_t)((wk * 12 + c) * 32);
                uint32_t ah[4], al[4];
                ldsm4(ah, abase + koff);
                ldsm4(al, abase + (uint32_t)(HPL * 2) + koff);
                mma16816(C, ah, wb0h[c], wb1h[c]);
                mma16816(C, ah, wb0l[c], wb1l[c]);
                mma16816(C, al, wb0h[c], wb1h[c]);
            }
        }
        *(float4*)&cst[wid * 128 + lane * 4] = make_float4(C[0], C[1], C[2], C[3]);
        __syncthreads();

        if (t < 96 && pos < N) {
            float pre[4];
#pragma unroll
            for (int g = 0; g < 4; ++g) {
                int r = g * 6 + hl;
                int wnn = r >> 3, cl = r & 7;
                int ln = (j & 7) * 4 + (cl >> 1);
                int rg = (cl & 1) + ((j >> 3) << 1);
                float sgd = gpre[g];
#pragma unroll
                for (int wq = 0; wq < 4; ++wq)
                    sgd += cst[(wq * 3 + wnn) * 128 + ln * 4 + rg];
                pre[g] = sgd;
            }
            float c2 = sigm(pre[1]) * c_reg + sigm(pre[0]) * tanhf(pre[2]);
            float h2 = sigm(pre[3]) * tanhf(c2);
            c_reg = c2;
            size_t o = (size_t)pos * FDIM + h_idx;
            SC_CS[o] = c2;
            __nv_bfloat16 hh = __float2bfloat16(h2);
            HBh[o] = hh;
            HBl[o] = __float2bfloat16(h2 - __bfloat162float(hh));
        }

        __threadfence();
        __syncthreads();
        if (t == 0) atomicExch(&SC_FLAG[b * 8], (unsigned)(s + 1));
    }
}

// ---------------- fused final cell: both directions in one pass ----------------
__global__ void k_final2(float* __restrict__ out, int N) {
    long long idx = (long long)blockIdx.x * blockDim.x + threadIdx.x;
    long long tot = (long long)N * FDIM;
    if (idx >= tot) return;
    int n = (int)(idx / FDIM), h = (int)(idx % FDIM);
    // forward (uses SC_G, c at n-9)
    {
        int ns = n - 9;
        float cin = (ns >= 0) ? SC_CS[(size_t)ns * FDIM + h] : 0.f;
        const float* g = SC_G + (size_t)n * G4;
        float gi = g[h], gf = g[FDIM + h], gg = g[2 * FDIM + h], go = g[3 * FDIM + h];
        float c2 = sigm(gf) * cin + sigm(gi) * tanhf(gg);
        out[(size_t)n * 1536 + h] = sigm(go) * tanhf(c2);
    }
    // reverse (uses SC_G2, c at n+9)
    {
        int ns = n + 9;
        float cin = (ns < N) ? SC_CS[(size_t)ns * FDIM + h] : 0.f;
        const float* g = SC_G2 + (size_t)n * G4;
        float gi = g[h], gf = g[FDIM + h], gg = g[2 * FDIM + h], go = g[3 * FDIM + h];
        float c2 = sigm(gf) * cin + sigm(gi) * tanhf(gg);
        out[(size_t)n * 1536 + 768 + h] = sigm(go) * tanhf(c2);
    }
}

// ---------------- launch ----------------
extern "C" void kernel_launch(void* const* d_in, const int* in_sizes, int n_in,
                              void* d_out, int out_size) {
    const float* x    = (const float*)d_in[0];
    const int*   dl   = (const int*)  d_in[1];
    const float* cw0  = (const float*)d_in[2];  const float* cb0 = (const float*)d_in[3];
    const float* cw1  = (const float*)d_in[4];  const float* cb1 = (const float*)d_in[5];
    const float* cw2  = (const float*)d_in[6];  const float* cb2 = (const float*)d_in[7];
    const float* Wih  = (const float*)d_in[8];  const float* Whh  = (const float*)d_in[9];
    const float* bih  = (const float*)d_in[10]; const float* bhh  = (const float*)d_in[11];
    const float* WihR = (const float*)d_in[12]; const float* WhhR = (const float*)d_in[13];
    const float* bihR = (const float*)d_in[14]; const float* bhhR = (const float*)d_in[15];
    float* out = (float*)d_out;

    int ndocs = in_sizes[1];
    int N = out_size / 1536;
    if (N > MAXN) N = MAXN;
    int nChunks = (N + 15) / 16;

    cudaFuncSetAttribute(k_mmconv_all, cudaFuncAttributeMaxDynamicSharedMemorySize, SMEM_MMA);
    cudaFuncSetAttribute(k_mmgate,     cudaFuncAttributeMaxDynamicSharedMemorySize, SMEM_MMA);
    cudaFuncSetAttribute(k_mmfinal,    cudaFuncAttributeMaxDynamicSharedMemorySize, SMEM_MMA);
    cudaFuncSetAttribute(k_scan,       cudaFuncAttributeMaxDynamicSharedMemorySize, SCAN_SMEM);

    // 0: PE + posidx + conv weight transpose
    k_prep<<<(15 * 256 * D_IN + 255) / 256, 256>>>(dl, ndocs, N, cw0, cw1, cw2);
    // 1: x + PE -> XB planes
    {
        long long tot = (long long)N * KPADX;
        k_addpe_cvt<<<(int)((tot + 255) / 256), 256>>>(x, N);
    }
    // 2: all weight conversions + flag reset
    k_wcvt<<<(int)((4LL * G4 * FDIM + 255) / 256), 256>>>(Wih, Whh, WihR, WhhR);

    int mt = (N + 127) / 128;
    // 3: all convs in one launch (mixed k7/k5/k3 CTAs pack into one wave train)
    {
        dim3 cg(mt, 6);
        k_mmconv_all<<<cg, 256, SMEM_MMA>>>(cb0, cb1, cb2, N);
    }
    // 4: pool + FB/PB planes
    {
        long long tot = (long long)N * FDIM;
        k_postconv<<<(int)((tot + 255) / 256), 256>>>(N);
    }

    // 5: gx = pool @ Wih^T + b_ih + b_hh
    {
        dim3 gg(mt, G4 / 128);
        k_mmgate<<<gg, 256, SMEM_MMA>>>(bih, bhh, N);
    }
    // 6: scan
    k_scan<<<128, 384, SCAN_SMEM>>>(N, nChunks);

    // 7: both final gate GEMMs in one launch (z = 0 fwd -> SC_G, z = 1 rev -> SC_G2)
    {
        dim3 gf(mt, G4 / 128, 2);
        k_mmfinal<<<gf, 256, SMEM_MMA>>>(bih, bhh, bihR, bhhR, N);
    }
    // 8: fused final cells -> out
    {
        long long tot = (long long)N * FDIM;
        k_final2<<<(int)((tot + 255) / 256), 256>>>(out, N);
    }
}